// round 1
// baseline (speedup 1.0000x reference)
#include <cuda_runtime.h>
#include <math.h>

#define NN 2048
#define BB 256
#define DD 512
#define TM 64
#define TN 64
#define KT 16
#define PAD 68            // padded smem row (float) : 68*4B = 272B, 16B-aligned rows
#define SOLVE_BLOCKS 128  // 32 m-tiles * 4 n-tiles, <= 148 SMs -> co-resident
#define MAXIT 300

// ---------------- device-global scratch (no allocations allowed) ------------
__device__ float  g_W[NN * NN];        // 16 MB
__device__ float  g_Vx[NN * BB];       // 2 MB
__device__ float  g_z[2][NN * BB];     // ping-pong state, 2x2 MB
__device__ double g_d2, g_n2;          // convergence accumulators
__device__ unsigned g_arrive;
__device__ unsigned g_release;
__device__ int g_stop;

// ---------------- init: zero z0 + reset barrier/flag state ------------------
__global__ void init_kernel() {
    int idx = blockIdx.x * blockDim.x + threadIdx.x;
    if (idx < NN * BB) g_z[0][idx] = 0.0f;
    if (idx == 0) {
        g_d2 = 0.0; g_n2 = 0.0;
        g_arrive = 0u; g_release = 0u;
        g_stop = 0;
    }
}

// ---------------- W = (1-m) I - A^T A + (S - S^T) ---------------------------
// A row-major (N,N): (A^T A)[i][j] = sum_k A[k][i] * A[k][j]
__global__ void __launch_bounds__(256) build_w_kernel(const float* __restrict__ A,
                                                      const float* __restrict__ S,
                                                      const float* __restrict__ m_raw) {
    __shared__ __align__(16) float As[KT][PAD];
    __shared__ __align__(16) float Bs[KT][PAD];
    const int i0 = blockIdx.x * TM;
    const int j0 = blockIdx.y * TN;
    const int tx = threadIdx.x & 15;
    const int ty = threadIdx.x >> 4;

    float acc[4][4];
#pragma unroll
    for (int a = 0; a < 4; a++)
#pragma unroll
        for (int b = 0; b < 4; b++) acc[a][b] = 0.0f;

    for (int k0 = 0; k0 < NN; k0 += KT) {
#pragma unroll
        for (int t = threadIdx.x; t < KT * TM; t += 256) {
            int r = t >> 6;     // k  (0..15)
            int c = t & 63;     // i/j (0..63)  -> coalesced
            As[r][c] = A[(k0 + r) * NN + i0 + c];
            Bs[r][c] = A[(k0 + r) * NN + j0 + c];
        }
        __syncthreads();
#pragma unroll
        for (int k = 0; k < KT; k++) {
            float4 av = *(const float4*)&As[k][ty * 4];
            float4 bv = *(const float4*)&Bs[k][tx * 4];
            float am[4] = {av.x, av.y, av.z, av.w};
            float bn[4] = {bv.x, bv.y, bv.z, bv.w};
#pragma unroll
            for (int mi = 0; mi < 4; mi++)
#pragma unroll
                for (int ni = 0; ni < 4; ni++) acc[mi][ni] += am[mi] * bn[ni];
        }
        __syncthreads();
    }

    const float m   = log1pf(expf(m_raw[0]));   // softplus
    const float omm = 1.0f - m;
#pragma unroll
    for (int mi = 0; mi < 4; mi++) {
        const int i = i0 + ty * 4 + mi;
#pragma unroll
        for (int ni = 0; ni < 4; ni++) {
            const int j = j0 + tx * 4 + ni;
            float w = -acc[mi][ni] + S[i * NN + j] - S[j * NN + i];
            if (i == j) w += omm;
            g_W[i * NN + j] = w;
        }
    }
}

// ---------------- Vx = U @ x^T + b  ((N,D)x(D,B) via NT gemm) ---------------
__global__ void __launch_bounds__(256) build_vx_kernel(const float* __restrict__ U,
                                                       const float* __restrict__ b,
                                                       const float* __restrict__ x) {
    __shared__ __align__(16) float Us[KT][PAD];
    __shared__ __align__(16) float Xs[KT][PAD];
    const int i0 = blockIdx.x * TM;   // over N
    const int j0 = blockIdx.y * TN;   // over B
    const int tx = threadIdx.x & 15;
    const int ty = threadIdx.x >> 4;

    float acc[4][4];
#pragma unroll
    for (int a = 0; a < 4; a++)
#pragma unroll
        for (int c = 0; c < 4; c++) acc[a][c] = 0.0f;

    for (int k0 = 0; k0 < DD; k0 += KT) {
#pragma unroll
        for (int t = threadIdx.x; t < KT * TM; t += 256) {
            int rr = t >> 4;    // row within tile (0..63)
            int cc = t & 15;    // k (0..15)
            Us[cc][rr] = U[(i0 + rr) * DD + k0 + cc];   // transposed store
            Xs[cc][rr] = x[(j0 + rr) * DD + k0 + cc];
        }
        __syncthreads();
#pragma unroll
        for (int k = 0; k < KT; k++) {
            float4 av = *(const float4*)&Us[k][ty * 4];
            float4 bv = *(const float4*)&Xs[k][tx * 4];
            float am[4] = {av.x, av.y, av.z, av.w};
            float bn[4] = {bv.x, bv.y, bv.z, bv.w};
#pragma unroll
            for (int mi = 0; mi < 4; mi++)
#pragma unroll
                for (int ni = 0; ni < 4; ni++) acc[mi][ni] += am[mi] * bn[ni];
        }
        __syncthreads();
    }
#pragma unroll
    for (int mi = 0; mi < 4; mi++) {
        const int i = i0 + ty * 4 + mi;
        const float bi = b[i];
#pragma unroll
        for (int ni = 0; ni < 4; ni++) {
            const int j = j0 + tx * 4 + ni;
            g_Vx[i * BB + j] = acc[mi][ni] + bi;
        }
    }
}

// ---------------- software grid barrier (all SOLVE_BLOCKS co-resident) ------
__device__ __forceinline__ void grid_barrier(unsigned& gen) {
    __syncthreads();
    if (threadIdx.x == 0) {
        gen++;
        __threadfence();
        unsigned prev = atomicAdd(&g_arrive, 1u);
        if (prev == SOLVE_BLOCKS - 1) {
            atomicExch(&g_arrive, 0u);
            __threadfence();
            atomicExch(&g_release, gen);
        } else {
            while (*(volatile unsigned*)&g_release < gen) { }
            __threadfence();
        }
    }
    __syncthreads();
}

// ---------------- persistent FB-splitting solver ----------------------------
__global__ void __launch_bounds__(256) solve_kernel(float* __restrict__ out) {
    const int bm = blockIdx.x >> 2;       // 0..31  (rows)
    const int bn = blockIdx.x & 3;        // 0..3   (batch cols)
    const int i0 = bm * TM;
    const int j0 = bn * TN;
    const int tx = threadIdx.x & 15;
    const int ty = threadIdx.x >> 4;

    __shared__ __align__(16) float Ws[KT][PAD];
    __shared__ __align__(16) float Zs[KT][PAD];
    __shared__ float sredD[8], sredN[8];

    unsigned gen = 0;
    int cur = 0;
    int it = 0;

    while (1) {
        it++;
        const float* __restrict__ z  = g_z[cur];
        float* __restrict__ zn = g_z[cur ^ 1];

        float acc[4][4];
#pragma unroll
        for (int a = 0; a < 4; a++)
#pragma unroll
            for (int c = 0; c < 4; c++) acc[a][c] = 0.0f;

        for (int k0 = 0; k0 < NN; k0 += KT) {
#pragma unroll
            for (int t = threadIdx.x; t < KT * TM; t += 256) {
                int rr = t >> 4;    // i within tile (0..63)
                int cc = t & 15;    // k (0..15)
                Ws[cc][rr] = g_W[(i0 + rr) * NN + k0 + cc];   // transposed store
            }
#pragma unroll
            for (int t = threadIdx.x; t < KT * TN; t += 256) {
                int r = t >> 6;     // k (0..15)
                int c = t & 63;     // j (0..63)  coalesced
                Zs[r][c] = z[(k0 + r) * BB + j0 + c];
            }
            __syncthreads();
#pragma unroll
            for (int k = 0; k < KT; k++) {
                float4 av = *(const float4*)&Ws[k][ty * 4];
                float4 bv = *(const float4*)&Zs[k][tx * 4];
                float am[4] = {av.x, av.y, av.z, av.w};
                float bn4[4] = {bv.x, bv.y, bv.z, bv.w};
#pragma unroll
                for (int mi = 0; mi < 4; mi++)
#pragma unroll
                    for (int ni = 0; ni < 4; ni++) acc[mi][ni] += am[mi] * bn4[ni];
            }
            __syncthreads();
        }

        // epilogue: zn = relu(0.9 z + 0.1 (Wz + Vx)), accumulate norms
        float d2 = 0.0f, n2 = 0.0f;
#pragma unroll
        for (int mi = 0; mi < 4; mi++) {
            const int i = i0 + ty * 4 + mi;
#pragma unroll
            for (int ni = 0; ni < 4; ni++) {
                const int j = j0 + tx * 4 + ni;
                const float zv = z[i * BB + j];
                float v = 0.9f * zv + 0.1f * (acc[mi][ni] + g_Vx[i * BB + j]);
                float r = v > 0.0f ? v : 0.0f;
                zn[i * BB + j] = r;
                const float dd = r - zv;
                d2 += dd * dd;
                n2 += zv * zv;
            }
        }
#pragma unroll
        for (int off = 16; off; off >>= 1) {
            d2 += __shfl_xor_sync(0xffffffffu, d2, off);
            n2 += __shfl_xor_sync(0xffffffffu, n2, off);
        }
        const int warp = threadIdx.x >> 5;
        if ((threadIdx.x & 31) == 0) { sredD[warp] = d2; sredN[warp] = n2; }
        __syncthreads();
        if (threadIdx.x == 0) {
            double Dd = 0.0, Nd = 0.0;
#pragma unroll
            for (int w = 0; w < 8; w++) { Dd += (double)sredD[w]; Nd += (double)sredN[w]; }
            atomicAdd(&g_d2, Dd);
            atomicAdd(&g_n2, Nd);
        }

        grid_barrier(gen);
        if (blockIdx.x == 0 && threadIdx.x == 0) {
            const double err = sqrt(g_d2) / (sqrt(g_n2) + 1e-12);
            g_stop = (it < MAXIT && err >= 1e-4) ? 0 : 1;
            g_d2 = 0.0; g_n2 = 0.0;
            __threadfence();
        }
        grid_barrier(gen);

        const int stop = *(volatile int*)&g_stop;
        cur ^= 1;                 // zn becomes current
        if (stop) break;
    }

    // write final z (this block's own tile) to output, (n,B) row-major
    const float* __restrict__ zf = g_z[cur];
#pragma unroll
    for (int mi = 0; mi < 4; mi++) {
        const int i = i0 + ty * 4 + mi;
#pragma unroll
        for (int ni = 0; ni < 4; ni++) {
            const int j = j0 + tx * 4 + ni;
            out[i * BB + j] = zf[i * BB + j];
        }
    }
}

// ---------------- entry -----------------------------------------------------
extern "C" void kernel_launch(void* const* d_in, const int* in_sizes, int n_in,
                              void* d_out, int out_size) {
    const float* A     = (const float*)d_in[0];   // (N,N)
    const float* S     = (const float*)d_in[1];   // (N,N)
    const float* m_raw = (const float*)d_in[2];   // (1,)
    const float* U     = (const float*)d_in[3];   // (N,D)
    const float* b     = (const float*)d_in[4];   // (N,)
    const float* x     = (const float*)d_in[5];   // (B,D)
    float* out = (float*)d_out;                   // (N,B)

    init_kernel<<<(NN * BB + 255) / 256, 256>>>();

    dim3 gw(NN / TM, NN / TN);
    build_w_kernel<<<gw, 256>>>(A, S, m_raw);

    dim3 gv(NN / TM, BB / TN);
    build_vx_kernel<<<gv, 256>>>(U, b, x);

    solve_kernel<<<SOLVE_BLOCKS, 256>>>(out);
}

// round 3
// speedup vs baseline: 6.2092x; 6.2092x over previous
#include <cuda_runtime.h>
#include <cuda_bf16.h>
#include <math.h>
#include <stdint.h>

#define NN 2048
#define BB 256
#define DD 512
#define MAXIT 300

#define SB 128           // persistent CTAs: 32 m-tiles x 4 n-tiles
#define MT 64            // CTA tile over hidden (i)
#define NT 64            // CTA tile over batch (j)
#define KC 64            // K per pipeline stage
#define NSTG 3
#define MAT_BYTES (64*128)          // 64 rows x 128B (64 bf16)
#define STG_BYTES (4*MAT_BYTES)     // Ahi, Alo, Bhi, Blo
#define OFF_AHI 0
#define OFF_ALO (1*MAT_BYTES)
#define OFF_BHI (2*MAT_BYTES)
#define OFF_BLO (3*MAT_BYTES)
#define DYN_SMEM (NSTG*STG_BYTES + 128)
#define NKC (NN/KC)      // 32

// ---------------- device-global scratch -------------------------------------
__device__ __nv_bfloat16 g_Whi[NN*NN];     // 8MB
__device__ __nv_bfloat16 g_Wlo[NN*NN];     // 8MB
__device__ float         g_Vx[NN*BB];      // [i][j]
__device__ __nv_bfloat16 g_zbh[2][BB*NN];  // z splits, [j][k], ping-pong
__device__ __nv_bfloat16 g_zbl[2][BB*NN];
__device__ double g_d2, g_n2;
__device__ unsigned g_arrive, g_release;
__device__ int g_stop;

// ---------------- helpers ---------------------------------------------------
__device__ __forceinline__ uint32_t smem_u32(const void* p) {
    uint32_t a;
    asm("{ .reg .u64 t; cvta.to.shared.u64 t, %1; cvt.u32.u64 %0, t; }"
        : "=r"(a) : "l"(p));
    return a;
}
__device__ __forceinline__ void cp16(uint32_t dst, const void* src) {
    asm volatile("cp.async.cg.shared.global [%0], [%1], 16;"
                 :: "r"(dst), "l"(src) : "memory");
}
#define CP_COMMIT() asm volatile("cp.async.commit_group;" ::: "memory")
#define CP_WAIT(n)  asm volatile("cp.async.wait_group %0;" :: "n"(n) : "memory")

__device__ __forceinline__ void ldsm4(uint32_t* r, uint32_t a) {
    asm volatile("ldmatrix.sync.aligned.m8n8.x4.shared.b16 {%0,%1,%2,%3}, [%4];"
                 : "=r"(r[0]), "=r"(r[1]), "=r"(r[2]), "=r"(r[3]) : "r"(a));
}
__device__ __forceinline__ void mma16816(float* c, const uint32_t* a,
                                         uint32_t b0, uint32_t b1) {
    asm volatile(
        "mma.sync.aligned.m16n8k16.row.col.f32.bf16.bf16.f32 "
        "{%0,%1,%2,%3}, {%4,%5,%6,%7}, {%8,%9}, {%0,%1,%2,%3};"
        : "+f"(c[0]), "+f"(c[1]), "+f"(c[2]), "+f"(c[3])
        : "r"(a[0]), "r"(a[1]), "r"(a[2]), "r"(a[3]), "r"(b0), "r"(b1));
}

// ---------------- init ------------------------------------------------------
__global__ void init_kernel() {
    int idx = blockIdx.x * blockDim.x + threadIdx.x;
    if (idx < BB * NN) {
        g_zbh[0][idx] = __float2bfloat16(0.0f);
        g_zbl[0][idx] = __float2bfloat16(0.0f);
    }
    if (idx == 0) {
        g_d2 = 0.0; g_n2 = 0.0;
        g_arrive = 0u; g_release = 0u; g_stop = 0;
    }
}

// ---------------- W = (1-m) I - A^T A + (S - S^T) -> bf16 hi/lo -------------
#define TMW 64
#define KTW 16
#define PADW 68
__global__ void __launch_bounds__(256) build_w_kernel(const float* __restrict__ A,
                                                      const float* __restrict__ S,
                                                      const float* __restrict__ m_raw) {
    __shared__ __align__(16) float As[KTW][PADW];
    __shared__ __align__(16) float Bs[KTW][PADW];
    const int i0 = blockIdx.x * TMW;
    const int j0 = blockIdx.y * TMW;
    const int tx = threadIdx.x & 15;
    const int ty = threadIdx.x >> 4;

    float acc[4][4];
#pragma unroll
    for (int a = 0; a < 4; a++)
#pragma unroll
        for (int b = 0; b < 4; b++) acc[a][b] = 0.0f;

    for (int k0 = 0; k0 < NN; k0 += KTW) {
#pragma unroll
        for (int t = threadIdx.x; t < KTW * TMW; t += 256) {
            int r = t >> 6, c = t & 63;
            As[r][c] = A[(k0 + r) * NN + i0 + c];
            Bs[r][c] = A[(k0 + r) * NN + j0 + c];
        }
        __syncthreads();
#pragma unroll
        for (int k = 0; k < KTW; k++) {
            float4 av = *(const float4*)&As[k][ty * 4];
            float4 bv = *(const float4*)&Bs[k][tx * 4];
            float am[4] = {av.x, av.y, av.z, av.w};
            float bn[4] = {bv.x, bv.y, bv.z, bv.w};
#pragma unroll
            for (int mi = 0; mi < 4; mi++)
#pragma unroll
                for (int ni = 0; ni < 4; ni++) acc[mi][ni] += am[mi] * bn[ni];
        }
        __syncthreads();
    }

    const float m = log1pf(expf(m_raw[0]));
    const float omm = 1.0f - m;
#pragma unroll
    for (int mi = 0; mi < 4; mi++) {
        const int i = i0 + ty * 4 + mi;
#pragma unroll
        for (int ni = 0; ni < 4; ni++) {
            const int j = j0 + tx * 4 + ni;
            float w = -acc[mi][ni] + S[i * NN + j] - S[j * NN + i];
            if (i == j) w += omm;
            __nv_bfloat16 hi = __float2bfloat16_rn(w);
            g_Whi[i * NN + j] = hi;
            g_Wlo[i * NN + j] = __float2bfloat16_rn(w - __bfloat162float(hi));
        }
    }
}

// ---------------- Vx[i][j] = (U @ x^T)[i][j] + b[i] -------------------------
__global__ void __launch_bounds__(256) build_vx_kernel(const float* __restrict__ U,
                                                       const float* __restrict__ b,
                                                       const float* __restrict__ x) {
    __shared__ __align__(16) float Us[KTW][PADW];
    __shared__ __align__(16) float Xs[KTW][PADW];
    const int i0 = blockIdx.x * TMW;   // over N
    const int j0 = blockIdx.y * TMW;   // over B
    const int tx = threadIdx.x & 15;
    const int ty = threadIdx.x >> 4;

    float acc[4][4];
#pragma unroll
    for (int a = 0; a < 4; a++)
#pragma unroll
        for (int c = 0; c < 4; c++) acc[a][c] = 0.0f;

    for (int k0 = 0; k0 < DD; k0 += KTW) {
#pragma unroll
        for (int t = threadIdx.x; t < KTW * TMW; t += 256) {
            int rr = t >> 4, cc = t & 15;
            Us[cc][rr] = U[(i0 + rr) * DD + k0 + cc];
            Xs[cc][rr] = x[(j0 + rr) * DD + k0 + cc];
        }
        __syncthreads();
#pragma unroll
        for (int k = 0; k < KTW; k++) {
            float4 av = *(const float4*)&Us[k][ty * 4];
            float4 bv = *(const float4*)&Xs[k][tx * 4];
            float am[4] = {av.x, av.y, av.z, av.w};
            float bn[4] = {bv.x, bv.y, bv.z, bv.w};
#pragma unroll
            for (int mi = 0; mi < 4; mi++)
#pragma unroll
                for (int ni = 0; ni < 4; ni++) acc[mi][ni] += am[mi] * bn[ni];
        }
        __syncthreads();
    }
#pragma unroll
    for (int mi = 0; mi < 4; mi++) {
        const int i = i0 + ty * 4 + mi;
        const float bi = b[i];
#pragma unroll
        for (int ni = 0; ni < 4; ni++) {
            const int j = j0 + tx * 4 + ni;
            g_Vx[i * BB + j] = acc[mi][ni] + bi;
        }
    }
}

// ---------------- software grid barrier -------------------------------------
__device__ __forceinline__ void grid_barrier(unsigned& gen) {
    __syncthreads();
    if (threadIdx.x == 0) {
        gen++;
        __threadfence();
        unsigned prev = atomicAdd(&g_arrive, 1u);
        if (prev == SB - 1) {
            atomicExch(&g_arrive, 0u);
            __threadfence();
            atomicExch(&g_release, gen);
        } else {
            while (*(volatile unsigned*)&g_release < gen) { }
            __threadfence();
        }
    }
    __syncthreads();
}

// ---------------- persistent bf16x3 mma.sync FB solver ----------------------
__global__ void __launch_bounds__(256, 1) solve_kernel(float* __restrict__ out) {
    extern __shared__ __align__(16) char dsm[];
    const uint32_t raw = smem_u32(dsm);
    const uint32_t sbase = (raw + 127u) & ~127u;

    __shared__ float sredD[8], sredN[8];

    const int tid = threadIdx.x;
    const int l = tid & 31;
    const int warp = tid >> 5;
    const int bm = blockIdx.x >> 2;       // 0..31
    const int bn = blockIdx.x & 3;        // 0..3
    const int i0 = bm * MT;
    const int j0 = bn * NT;
    const int wm = (warp >> 2) * 32;      // warp m offset: 0 / 32
    const int wn = (warp & 3) * 16;       // warp n offset: 0/16/32/48

    // per-lane fragment geometry
    const int r7 = l & 7;
    const int rowA0 = wm + r7 + ((l >> 3) & 1) * 8;   // + f*16
    const int kgAsel = (l >> 4) & 1;
    const int rowB = wn + r7 + ((l >> 4) & 1) * 8;
    const int kgBsel = (l >> 3) & 1;

    // loader geometry: thread handles 2 (row, kg) chunks per matrix per stage
    const int ld_row0 = tid >> 3;           // 0..31
    const int ld_kg = tid & 7;              // 0..7
    const uint32_t ld_sw0 = ((uint32_t)(ld_kg ^ (ld_row0 & 7))) << 4;
    const int ld_row1 = ld_row0 + 32;
    const uint32_t ld_sw1 = ((uint32_t)(ld_kg ^ (ld_row1 & 7))) << 4;

    // epilogue geometry: element (i, j) ownership (16 elements per thread)
    // f in {0,1}: m16; g in {0,1}: n8; h in {0,1}: +8 rows
    // i = i0 + wm + f*16 + h*8 + l/4 ; j = j0 + wn + g*8 + (l&3)*2 + {0,1}

    // fp32 state in registers
    float zr[2][2][2][2];   // [f][g][h][pair]
    float vx[2][2][2][2];
#pragma unroll
    for (int f = 0; f < 2; f++)
#pragma unroll
        for (int g = 0; g < 2; g++)
#pragma unroll
            for (int h = 0; h < 2; h++) {
                const int i = i0 + wm + f * 16 + h * 8 + (l >> 2);
                const int j = j0 + wn + g * 8 + (l & 3) * 2;
                float2 v = *(const float2*)&g_Vx[i * BB + j];
                vx[f][g][h][0] = v.x; vx[f][g][h][1] = v.y;
                zr[f][g][h][0] = 0.0f; zr[f][g][h][1] = 0.0f;
            }

    unsigned gen = 0;
    int cur = 0, it = 0;

    while (1) {
        it++;
        const __nv_bfloat16* __restrict__ zh = g_zbh[cur];
        const __nv_bfloat16* __restrict__ zl = g_zbl[cur];

        float c[2][2][4];
#pragma unroll
        for (int f = 0; f < 2; f++)
#pragma unroll
            for (int g = 0; g < 2; g++)
#pragma unroll
                for (int q = 0; q < 4; q++) c[f][g][q] = 0.0f;

        // ---- prologue: stages 0,1 ----
#pragma unroll
        for (int s = 0; s < NSTG - 1; s++) {
            const int k0 = s * KC;
            const uint32_t sb = sbase + s * STG_BYTES;
            const long gW0 = (long)(i0 + ld_row0) * NN + k0 + ld_kg * 8;
            const long gW1 = (long)(i0 + ld_row1) * NN + k0 + ld_kg * 8;
            const long gZ0 = (long)(j0 + ld_row0) * NN + k0 + ld_kg * 8;
            const long gZ1 = (long)(j0 + ld_row1) * NN + k0 + ld_kg * 8;
            const uint32_t d0 = (uint32_t)ld_row0 * 128 + ld_sw0;
            const uint32_t d1 = (uint32_t)ld_row1 * 128 + ld_sw1;
            cp16(sb + OFF_AHI + d0, g_Whi + gW0);
            cp16(sb + OFF_AHI + d1, g_Whi + gW1);
            cp16(sb + OFF_ALO + d0, g_Wlo + gW0);
            cp16(sb + OFF_ALO + d1, g_Wlo + gW1);
            cp16(sb + OFF_BHI + d0, zh + gZ0);
            cp16(sb + OFF_BHI + d1, zh + gZ1);
            cp16(sb + OFF_BLO + d0, zl + gZ0);
            cp16(sb + OFF_BLO + d1, zl + gZ1);
            CP_COMMIT();
        }

        for (int kc = 0; kc < NKC; kc++) {
            if (kc + NSTG - 1 < NKC) {
                const int s = (kc + NSTG - 1) % NSTG;
                const int k0 = (kc + NSTG - 1) * KC;
                const uint32_t sb = sbase + s * STG_BYTES;
                const long gW0 = (long)(i0 + ld_row0) * NN + k0 + ld_kg * 8;
                const long gW1 = (long)(i0 + ld_row1) * NN + k0 + ld_kg * 8;
                const long gZ0 = (long)(j0 + ld_row0) * NN + k0 + ld_kg * 8;
                const long gZ1 = (long)(j0 + ld_row1) * NN + k0 + ld_kg * 8;
                const uint32_t d0 = (uint32_t)ld_row0 * 128 + ld_sw0;
                const uint32_t d1 = (uint32_t)ld_row1 * 128 + ld_sw1;
                cp16(sb + OFF_AHI + d0, g_Whi + gW0);
                cp16(sb + OFF_AHI + d1, g_Whi + gW1);
                cp16(sb + OFF_ALO + d0, g_Wlo + gW0);
                cp16(sb + OFF_ALO + d1, g_Wlo + gW1);
                cp16(sb + OFF_BHI + d0, zh + gZ0);
                cp16(sb + OFF_BHI + d1, zh + gZ1);
                cp16(sb + OFF_BLO + d0, zl + gZ0);
                cp16(sb + OFF_BLO + d1, zl + gZ1);
            }
            CP_COMMIT();
            CP_WAIT(NSTG - 1);
            __syncthreads();

            const uint32_t sb = sbase + (kc % NSTG) * STG_BYTES;
#pragma unroll
            for (int s4 = 0; s4 < 4; s4++) {
                const int kg0 = s4 * 2;
                const uint32_t swA = (uint32_t)((kg0 + kgAsel) ^ r7) << 4;
                const uint32_t swB = (uint32_t)((kg0 + kgBsel) ^ r7) << 4;
                uint32_t ah0[4], ah1[4], al0[4], al1[4], bh[4], bl[4];
                ldsm4(ah0, sb + OFF_AHI + (uint32_t)rowA0 * 128 + swA);
                ldsm4(ah1, sb + OFF_AHI + (uint32_t)(rowA0 + 16) * 128 + swA);
                ldsm4(al0, sb + OFF_ALO + (uint32_t)rowA0 * 128 + swA);
                ldsm4(al1, sb + OFF_ALO + (uint32_t)(rowA0 + 16) * 128 + swA);
                ldsm4(bh, sb + OFF_BHI + (uint32_t)rowB * 128 + swB);
                ldsm4(bl, sb + OFF_BLO + (uint32_t)rowB * 128 + swB);

                mma16816(c[0][0], ah0, bh[0], bh[1]);
                mma16816(c[0][1], ah0, bh[2], bh[3]);
                mma16816(c[1][0], ah1, bh[0], bh[1]);
                mma16816(c[1][1], ah1, bh[2], bh[3]);
                mma16816(c[0][0], ah0, bl[0], bl[1]);
                mma16816(c[0][1], ah0, bl[2], bl[3]);
                mma16816(c[1][0], ah1, bl[0], bl[1]);
                mma16816(c[1][1], ah1, bl[2], bl[3]);
                mma16816(c[0][0], al0, bh[0], bh[1]);
                mma16816(c[0][1], al0, bh[2], bh[3]);
                mma16816(c[1][0], al1, bh[0], bh[1]);
                mma16816(c[1][1], al1, bh[2], bh[3]);
            }
            __syncthreads();
        }

        // ---- epilogue: z' = relu(0.9 z + 0.1 (Wz + Vx)) ----
        __nv_bfloat16* __restrict__ zhn = g_zbh[cur ^ 1];
        __nv_bfloat16* __restrict__ zln = g_zbl[cur ^ 1];
        float d2 = 0.0f, n2 = 0.0f;
#pragma unroll
        for (int f = 0; f < 2; f++)
#pragma unroll
            for (int g = 0; g < 2; g++)
#pragma unroll
                for (int h = 0; h < 2; h++) {
                    const int i = i0 + wm + f * 16 + h * 8 + (l >> 2);
                    const int j = j0 + wn + g * 8 + (l & 3) * 2;
#pragma unroll
                    for (int p = 0; p < 2; p++) {
                        const float zv = zr[f][g][h][p];
                        float v = 0.9f * zv +
                                  0.1f * (c[f][g][h * 2 + p] + vx[f][g][h][p]);
                        float r = v > 0.0f ? v : 0.0f;
                        zr[f][g][h][p] = r;
                        __nv_bfloat16 hi = __float2bfloat16_rn(r);
                        zhn[(j + p) * NN + i] = hi;
                        zln[(j + p) * NN + i] =
                            __float2bfloat16_rn(r - __bfloat162float(hi));
                        const float dd = r - zv;
                        d2 += dd * dd;
                        n2 += zv * zv;
                    }
                }
#pragma unroll
        for (int off = 16; off; off >>= 1) {
            d2 += __shfl_xor_sync(0xffffffffu, d2, off);
            n2 += __shfl_xor_sync(0xffffffffu, n2, off);
        }
        if (l == 0) { sredD[warp] = d2; sredN[warp] = n2; }
        __syncthreads();
        if (tid == 0) {
            double Dd = 0.0, Nd = 0.0;
#pragma unroll
            for (int w = 0; w < 8; w++) { Dd += (double)sredD[w]; Nd += (double)sredN[w]; }
            atomicAdd(&g_d2, Dd);
            atomicAdd(&g_n2, Nd);
        }

        grid_barrier(gen);
        if (blockIdx.x == 0 && tid == 0) {
            const double err = sqrt(g_d2) / (sqrt(g_n2) + 1e-12);
            g_stop = (it < MAXIT && err >= 1e-4) ? 0 : 1;
            g_d2 = 0.0; g_n2 = 0.0;
            __threadfence();
        }
        grid_barrier(gen);

        const int stop = *(volatile int*)&g_stop;
        cur ^= 1;
        if (stop) break;
    }

    // write final z (register-resident) to out[i][j]
#pragma unroll
    for (int f = 0; f < 2; f++)
#pragma unroll
        for (int g = 0; g < 2; g++)
#pragma unroll
            for (int h = 0; h < 2; h++) {
                const int i = i0 + wm + f * 16 + h * 8 + (l >> 2);
                const int j = j0 + wn + g * 8 + (l & 3) * 2;
                float2 v;
                v.x = zr[f][g][h][0];
                v.y = zr[f][g][h][1];
                *(float2*)&out[i * BB + j] = v;
            }
}

// ---------------- entry -----------------------------------------------------
extern "C" void kernel_launch(void* const* d_in, const int* in_sizes, int n_in,
                              void* d_out, int out_size) {
    const float* A     = (const float*)d_in[0];
    const float* S     = (const float*)d_in[1];
    const float* m_raw = (const float*)d_in[2];
    const float* U     = (const float*)d_in[3];
    const float* b     = (const float*)d_in[4];
    const float* x     = (const float*)d_in[5];
    float* out = (float*)d_out;

    cudaFuncSetAttribute(solve_kernel,
                         cudaFuncAttributeMaxDynamicSharedMemorySize, DYN_SMEM);

    init_kernel<<<(BB * NN + 255) / 256, 256>>>();

    dim3 gw(NN / TMW, NN / TMW);
    build_w_kernel<<<gw, 256>>>(A, S, m_raw);

    dim3 gv(NN / TMW, BB / TMW);
    build_vx_kernel<<<gv, 256>>>(U, b, x);

    solve_kernel<<<SB, 256, DYN_SMEM>>>(out);
}

// round 4
// speedup vs baseline: 6.2272x; 1.0029x over previous
#include <cuda_runtime.h>
#include <cuda_bf16.h>
#include <math.h>
#include <stdint.h>

#define NN 2048
#define BB 256
#define DD 512
#define MAXIT 300

#define SB 128           // persistent CTAs: 32 m-tiles x 4 n-tiles
#define MT 64            // CTA tile over hidden (i)
#define NT 64            // CTA tile over batch (j)
#define KC 64            // K per pipeline stage
#define NSTG 3
#define MAT_BYTES (64*128)          // 64 rows x 128B (64 bf16)
#define STG_BYTES (4*MAT_BYTES)     // Ahi, Alo, Bhi, Blo
#define OFF_AHI 0
#define OFF_ALO (1*MAT_BYTES)
#define OFF_BHI (2*MAT_BYTES)
#define OFF_BLO (3*MAT_BYTES)
#define DYN_SMEM (NSTG*STG_BYTES + 128)
#define NKC (NN/KC)      // 32

// ---------------- device-global scratch -------------------------------------
__device__ __nv_bfloat16 g_Whi[NN*NN];     // 8MB
__device__ __nv_bfloat16 g_Wlo[NN*NN];     // 8MB
__device__ float         g_Vx[NN*BB];      // [i][j]
__device__ __nv_bfloat16 g_zbh[2][BB*NN];  // z splits, [j][k], ping-pong
__device__ __nv_bfloat16 g_zbl[2][BB*NN];
__device__ double g_d2, g_n2;
__device__ unsigned g_arrive, g_release;
__device__ int g_stop;

// ---------------- helpers ---------------------------------------------------
__device__ __forceinline__ uint32_t smem_u32(const void* p) {
    uint32_t a;
    asm("{ .reg .u64 t; cvta.to.shared.u64 t, %1; cvt.u32.u64 %0, t; }"
        : "=r"(a) : "l"(p));
    return a;
}
__device__ __forceinline__ void cp16(uint32_t dst, const void* src) {
    asm volatile("cp.async.cg.shared.global [%0], [%1], 16;"
                 :: "r"(dst), "l"(src) : "memory");
}
#define CP_COMMIT() asm volatile("cp.async.commit_group;" ::: "memory")
#define CP_WAIT(n)  asm volatile("cp.async.wait_group %0;" :: "n"(n) : "memory")

__device__ __forceinline__ void ldsm4(uint32_t* r, uint32_t a) {
    asm volatile("ldmatrix.sync.aligned.m8n8.x4.shared.b16 {%0,%1,%2,%3}, [%4];"
                 : "=r"(r[0]), "=r"(r[1]), "=r"(r[2]), "=r"(r[3]) : "r"(a));
}
__device__ __forceinline__ void mma16816(float* c, const uint32_t* a,
                                         uint32_t b0, uint32_t b1) {
    asm volatile(
        "mma.sync.aligned.m16n8k16.row.col.f32.bf16.bf16.f32 "
        "{%0,%1,%2,%3}, {%4,%5,%6,%7}, {%8,%9}, {%0,%1,%2,%3};"
        : "+f"(c[0]), "+f"(c[1]), "+f"(c[2]), "+f"(c[3])
        : "r"(a[0]), "r"(a[1]), "r"(a[2]), "r"(a[3]), "r"(b0), "r"(b1));
}

// ---------------- init ------------------------------------------------------
__global__ void init_kernel() {
    int idx = blockIdx.x * blockDim.x + threadIdx.x;
    if (idx < BB * NN) {
        g_zbh[0][idx] = __float2bfloat16(0.0f);
        g_zbl[0][idx] = __float2bfloat16(0.0f);
    }
    if (idx == 0) {
        g_d2 = 0.0; g_n2 = 0.0;
        g_arrive = 0u; g_release = 0u; g_stop = 0;
    }
}

// ---------------- W = (1-m) I - A^T A + (S - S^T) -> bf16 hi/lo -------------
#define TMW 64
#define KTW 16
#define PADW 68
__global__ void __launch_bounds__(256) build_w_kernel(const float* __restrict__ A,
                                                      const float* __restrict__ S,
                                                      const float* __restrict__ m_raw) {
    __shared__ __align__(16) float As[KTW][PADW];
    __shared__ __align__(16) float Bs[KTW][PADW];
    const int i0 = blockIdx.x * TMW;
    const int j0 = blockIdx.y * TMW;
    const int tx = threadIdx.x & 15;
    const int ty = threadIdx.x >> 4;

    float acc[4][4];
#pragma unroll
    for (int a = 0; a < 4; a++)
#pragma unroll
        for (int b = 0; b < 4; b++) acc[a][b] = 0.0f;

    for (int k0 = 0; k0 < NN; k0 += KTW) {
#pragma unroll
        for (int t = threadIdx.x; t < KTW * TMW; t += 256) {
            int r = t >> 6, c = t & 63;
            As[r][c] = A[(k0 + r) * NN + i0 + c];
            Bs[r][c] = A[(k0 + r) * NN + j0 + c];
        }
        __syncthreads();
#pragma unroll
        for (int k = 0; k < KTW; k++) {
            float4 av = *(const float4*)&As[k][ty * 4];
            float4 bv = *(const float4*)&Bs[k][tx * 4];
            float am[4] = {av.x, av.y, av.z, av.w};
            float bn[4] = {bv.x, bv.y, bv.z, bv.w};
#pragma unroll
            for (int mi = 0; mi < 4; mi++)
#pragma unroll
                for (int ni = 0; ni < 4; ni++) acc[mi][ni] += am[mi] * bn[ni];
        }
        __syncthreads();
    }

    const float m = log1pf(expf(m_raw[0]));
    const float omm = 1.0f - m;
#pragma unroll
    for (int mi = 0; mi < 4; mi++) {
        const int i = i0 + ty * 4 + mi;
#pragma unroll
        for (int ni = 0; ni < 4; ni++) {
            const int j = j0 + tx * 4 + ni;
            float w = -acc[mi][ni] + S[i * NN + j] - S[j * NN + i];
            if (i == j) w += omm;
            __nv_bfloat16 hi = __float2bfloat16_rn(w);
            g_Whi[i * NN + j] = hi;
            g_Wlo[i * NN + j] = __float2bfloat16_rn(w - __bfloat162float(hi));
        }
    }
}

// ---------------- Vx[i][j] = (U @ x^T)[i][j] + b[i] -------------------------
__global__ void __launch_bounds__(256) build_vx_kernel(const float* __restrict__ U,
                                                       const float* __restrict__ b,
                                                       const float* __restrict__ x) {
    __shared__ __align__(16) float Us[KTW][PADW];
    __shared__ __align__(16) float Xs[KTW][PADW];
    const int i0 = blockIdx.x * TMW;   // over N
    const int j0 = blockIdx.y * TMW;   // over B
    const int tx = threadIdx.x & 15;
    const int ty = threadIdx.x >> 4;

    float acc[4][4];
#pragma unroll
    for (int a = 0; a < 4; a++)
#pragma unroll
        for (int c = 0; c < 4; c++) acc[a][c] = 0.0f;

    for (int k0 = 0; k0 < DD; k0 += KTW) {
#pragma unroll
        for (int t = threadIdx.x; t < KTW * TMW; t += 256) {
            int rr = t >> 4, cc = t & 15;
            Us[cc][rr] = U[(i0 + rr) * DD + k0 + cc];
            Xs[cc][rr] = x[(j0 + rr) * DD + k0 + cc];
        }
        __syncthreads();
#pragma unroll
        for (int k = 0; k < KTW; k++) {
            float4 av = *(const float4*)&Us[k][ty * 4];
            float4 bv = *(const float4*)&Xs[k][tx * 4];
            float am[4] = {av.x, av.y, av.z, av.w};
            float bn[4] = {bv.x, bv.y, bv.z, bv.w};
#pragma unroll
            for (int mi = 0; mi < 4; mi++)
#pragma unroll
                for (int ni = 0; ni < 4; ni++) acc[mi][ni] += am[mi] * bn[ni];
        }
        __syncthreads();
    }
#pragma unroll
    for (int mi = 0; mi < 4; mi++) {
        const int i = i0 + ty * 4 + mi;
        const float bi = b[i];
#pragma unroll
        for (int ni = 0; ni < 4; ni++) {
            const int j = j0 + tx * 4 + ni;
            g_Vx[i * BB + j] = acc[mi][ni] + bi;
        }
    }
}

// ---------------- software grid barrier -------------------------------------
__device__ __forceinline__ void grid_barrier(unsigned& gen) {
    __syncthreads();
    if (threadIdx.x == 0) {
        gen++;
        __threadfence();
        unsigned prev = atomicAdd(&g_arrive, 1u);
        if (prev == SB - 1) {
            atomicExch(&g_arrive, 0u);
            __threadfence();
            atomicExch(&g_release, gen);
        } else {
            while (*(volatile unsigned*)&g_release < gen) { }
            __threadfence();
        }
    }
    __syncthreads();
}

// ---------------- persistent bf16x3 mma.sync FB solver ----------------------
__global__ void __launch_bounds__(256, 1) solve_kernel(float* __restrict__ out) {
    extern __shared__ __align__(16) char dsm[];
    const uint32_t raw = smem_u32(dsm);
    const uint32_t sbase = (raw + 127u) & ~127u;

    __shared__ float sredD[8], sredN[8];

    const int tid = threadIdx.x;
    const int l = tid & 31;
    const int warp = tid >> 5;
    const int bm = blockIdx.x >> 2;       // 0..31
    const int bn = blockIdx.x & 3;        // 0..3
    const int i0 = bm * MT;
    const int j0 = bn * NT;
    const int wm = (warp >> 2) * 32;      // warp m offset: 0 / 32
    const int wn = (warp & 3) * 16;       // warp n offset: 0/16/32/48

    // per-lane fragment geometry
    const int r7 = l & 7;
    const int rowA0 = wm + r7 + ((l >> 3) & 1) * 8;   // + f*16
    const int kgAsel = (l >> 4) & 1;
    const int rowB = wn + r7 + ((l >> 4) & 1) * 8;
    const int kgBsel = (l >> 3) & 1;

    // loader geometry: thread handles 2 (row, kg) chunks per matrix per stage
    const int ld_row0 = tid >> 3;           // 0..31
    const int ld_kg = tid & 7;              // 0..7
    const uint32_t ld_sw0 = ((uint32_t)(ld_kg ^ (ld_row0 & 7))) << 4;
    const int ld_row1 = ld_row0 + 32;
    const uint32_t ld_sw1 = ((uint32_t)(ld_kg ^ (ld_row1 & 7))) << 4;

    // epilogue geometry: element (i, j) ownership (16 elements per thread)
    // f in {0,1}: m16; g in {0,1}: n8; h in {0,1}: +8 rows
    // i = i0 + wm + f*16 + h*8 + l/4 ; j = j0 + wn + g*8 + (l&3)*2 + {0,1}

    // fp32 state in registers
    float zr[2][2][2][2];   // [f][g][h][pair]
    float vx[2][2][2][2];
#pragma unroll
    for (int f = 0; f < 2; f++)
#pragma unroll
        for (int g = 0; g < 2; g++)
#pragma unroll
            for (int h = 0; h < 2; h++) {
                const int i = i0 + wm + f * 16 + h * 8 + (l >> 2);
                const int j = j0 + wn + g * 8 + (l & 3) * 2;
                float2 v = *(const float2*)&g_Vx[i * BB + j];
                vx[f][g][h][0] = v.x; vx[f][g][h][1] = v.y;
                zr[f][g][h][0] = 0.0f; zr[f][g][h][1] = 0.0f;
            }

    unsigned gen = 0;
    int cur = 0, it = 0;

    while (1) {
        it++;
        const __nv_bfloat16* __restrict__ zh = g_zbh[cur];
        const __nv_bfloat16* __restrict__ zl = g_zbl[cur];

        float c[2][2][4];
#pragma unroll
        for (int f = 0; f < 2; f++)
#pragma unroll
            for (int g = 0; g < 2; g++)
#pragma unroll
                for (int q = 0; q < 4; q++) c[f][g][q] = 0.0f;

        // ---- prologue: stages 0,1 ----
#pragma unroll
        for (int s = 0; s < NSTG - 1; s++) {
            const int k0 = s * KC;
            const uint32_t sb = sbase + s * STG_BYTES;
            const long gW0 = (long)(i0 + ld_row0) * NN + k0 + ld_kg * 8;
            const long gW1 = (long)(i0 + ld_row1) * NN + k0 + ld_kg * 8;
            const long gZ0 = (long)(j0 + ld_row0) * NN + k0 + ld_kg * 8;
            const long gZ1 = (long)(j0 + ld_row1) * NN + k0 + ld_kg * 8;
            const uint32_t d0 = (uint32_t)ld_row0 * 128 + ld_sw0;
            const uint32_t d1 = (uint32_t)ld_row1 * 128 + ld_sw1;
            cp16(sb + OFF_AHI + d0, g_Whi + gW0);
            cp16(sb + OFF_AHI + d1, g_Whi + gW1);
            cp16(sb + OFF_ALO + d0, g_Wlo + gW0);
            cp16(sb + OFF_ALO + d1, g_Wlo + gW1);
            cp16(sb + OFF_BHI + d0, zh + gZ0);
            cp16(sb + OFF_BHI + d1, zh + gZ1);
            cp16(sb + OFF_BLO + d0, zl + gZ0);
            cp16(sb + OFF_BLO + d1, zl + gZ1);
            CP_COMMIT();
        }

        for (int kc = 0; kc < NKC; kc++) {
            if (kc + NSTG - 1 < NKC) {
                const int s = (kc + NSTG - 1) % NSTG;
                const int k0 = (kc + NSTG - 1) * KC;
                const uint32_t sb = sbase + s * STG_BYTES;
                const long gW0 = (long)(i0 + ld_row0) * NN + k0 + ld_kg * 8;
                const long gW1 = (long)(i0 + ld_row1) * NN + k0 + ld_kg * 8;
                const long gZ0 = (long)(j0 + ld_row0) * NN + k0 + ld_kg * 8;
                const long gZ1 = (long)(j0 + ld_row1) * NN + k0 + ld_kg * 8;
                const uint32_t d0 = (uint32_t)ld_row0 * 128 + ld_sw0;
                const uint32_t d1 = (uint32_t)ld_row1 * 128 + ld_sw1;
                cp16(sb + OFF_AHI + d0, g_Whi + gW0);
                cp16(sb + OFF_AHI + d1, g_Whi + gW1);
                cp16(sb + OFF_ALO + d0, g_Wlo + gW0);
                cp16(sb + OFF_ALO + d1, g_Wlo + gW1);
                cp16(sb + OFF_BHI + d0, zh + gZ0);
                cp16(sb + OFF_BHI + d1, zh + gZ1);
                cp16(sb + OFF_BLO + d0, zl + gZ0);
                cp16(sb + OFF_BLO + d1, zl + gZ1);
            }
            CP_COMMIT();
            CP_WAIT(NSTG - 1);
            __syncthreads();

            const uint32_t sb = sbase + (kc % NSTG) * STG_BYTES;
#pragma unroll
            for (int s4 = 0; s4 < 4; s4++) {
                const int kg0 = s4 * 2;
                const uint32_t swA = (uint32_t)((kg0 + kgAsel) ^ r7) << 4;
                const uint32_t swB = (uint32_t)((kg0 + kgBsel) ^ r7) << 4;
                uint32_t ah0[4], ah1[4], al0[4], al1[4], bh[4], bl[4];
                ldsm4(ah0, sb + OFF_AHI + (uint32_t)rowA0 * 128 + swA);
                ldsm4(ah1, sb + OFF_AHI + (uint32_t)(rowA0 + 16) * 128 + swA);
                ldsm4(al0, sb + OFF_ALO + (uint32_t)rowA0 * 128 + swA);
                ldsm4(al1, sb + OFF_ALO + (uint32_t)(rowA0 + 16) * 128 + swA);
                ldsm4(bh, sb + OFF_BHI + (uint32_t)rowB * 128 + swB);
                ldsm4(bl, sb + OFF_BLO + (uint32_t)rowB * 128 + swB);

                mma16816(c[0][0], ah0, bh[0], bh[1]);
                mma16816(c[0][1], ah0, bh[2], bh[3]);
                mma16816(c[1][0], ah1, bh[0], bh[1]);
                mma16816(c[1][1], ah1, bh[2], bh[3]);
                mma16816(c[0][0], ah0, bl[0], bl[1]);
                mma16816(c[0][1], ah0, bl[2], bl[3]);
                mma16816(c[1][0], ah1, bl[0], bl[1]);
                mma16816(c[1][1], ah1, bl[2], bl[3]);
                mma16816(c[0][0], al0, bh[0], bh[1]);
                mma16816(c[0][1], al0, bh[2], bh[3]);
                mma16816(c[1][0], al1, bh[0], bh[1]);
                mma16816(c[1][1], al1, bh[2], bh[3]);
            }
            __syncthreads();
        }

        // ---- epilogue: z' = relu(0.9 z + 0.1 (Wz + Vx)) ----
        __nv_bfloat16* __restrict__ zhn = g_zbh[cur ^ 1];
        __nv_bfloat16* __restrict__ zln = g_zbl[cur ^ 1];
        float d2 = 0.0f, n2 = 0.0f;
#pragma unroll
        for (int f = 0; f < 2; f++)
#pragma unroll
            for (int g = 0; g < 2; g++)
#pragma unroll
                for (int h = 0; h < 2; h++) {
                    const int i = i0 + wm + f * 16 + h * 8 + (l >> 2);
                    const int j = j0 + wn + g * 8 + (l & 3) * 2;
#pragma unroll
                    for (int p = 0; p < 2; p++) {
                        const float zv = zr[f][g][h][p];
                        float v = 0.9f * zv +
                                  0.1f * (c[f][g][h * 2 + p] + vx[f][g][h][p]);
                        float r = v > 0.0f ? v : 0.0f;
                        zr[f][g][h][p] = r;
                        __nv_bfloat16 hi = __float2bfloat16_rn(r);
                        zhn[(j + p) * NN + i] = hi;
                        zln[(j + p) * NN + i] =
                            __float2bfloat16_rn(r - __bfloat162float(hi));
                        const float dd = r - zv;
                        d2 += dd * dd;
                        n2 += zv * zv;
                    }
                }
#pragma unroll
        for (int off = 16; off; off >>= 1) {
            d2 += __shfl_xor_sync(0xffffffffu, d2, off);
            n2 += __shfl_xor_sync(0xffffffffu, n2, off);
        }
        if (l == 0) { sredD[warp] = d2; sredN[warp] = n2; }
        __syncthreads();
        if (tid == 0) {
            double Dd = 0.0, Nd = 0.0;
#pragma unroll
            for (int w = 0; w < 8; w++) { Dd += (double)sredD[w]; Nd += (double)sredN[w]; }
            atomicAdd(&g_d2, Dd);
            atomicAdd(&g_n2, Nd);
        }

        grid_barrier(gen);
        if (blockIdx.x == 0 && tid == 0) {
            const double err = sqrt(g_d2) / (sqrt(g_n2) + 1e-12);
            g_stop = (it < MAXIT && err >= 1e-4) ? 0 : 1;
            g_d2 = 0.0; g_n2 = 0.0;
            __threadfence();
        }
        grid_barrier(gen);

        const int stop = *(volatile int*)&g_stop;
        cur ^= 1;
        if (stop) break;
    }

    // write final z (register-resident) to out[i][j]
#pragma unroll
    for (int f = 0; f < 2; f++)
#pragma unroll
        for (int g = 0; g < 2; g++)
#pragma unroll
            for (int h = 0; h < 2; h++) {
                const int i = i0 + wm + f * 16 + h * 8 + (l >> 2);
                const int j = j0 + wn + g * 8 + (l & 3) * 2;
                float2 v;
                v.x = zr[f][g][h][0];
                v.y = zr[f][g][h][1];
                *(float2*)&out[i * BB + j] = v;
            }
}

// ---------------- entry -----------------------------------------------------
extern "C" void kernel_launch(void* const* d_in, const int* in_sizes, int n_in,
                              void* d_out, int out_size) {
    const float* A     = (const float*)d_in[0];
    const float* S     = (const float*)d_in[1];
    const float* m_raw = (const float*)d_in[2];
    const float* U     = (const float*)d_in[3];
    const float* b     = (const float*)d_in[4];
    const float* x     = (const float*)d_in[5];
    float* out = (float*)d_out;

    cudaFuncSetAttribute(solve_kernel,
                         cudaFuncAttributeMaxDynamicSharedMemorySize, DYN_SMEM);

    init_kernel<<<(BB * NN + 255) / 256, 256>>>();

    dim3 gw(NN / TMW, NN / TMW);
    build_w_kernel<<<gw, 256>>>(A, S, m_raw);

    dim3 gv(NN / TMW, BB / TMW);
    build_vx_kernel<<<gv, 256>>>(U, b, x);

    solve_kernel<<<SB, 256, DYN_SMEM>>>(out);
}

// round 5
// speedup vs baseline: 7.6669x; 1.2312x over previous
#include <cuda_runtime.h>
#include <cuda_bf16.h>
#include <math.h>
#include <stdint.h>

#define NN 2048
#define BB 256
#define DD 512
#define MAXIT 300

#define SB 128
#define KC 64
#define NSTG 4
#define MATB (64*128)
#define STGB (4*MATB)
#define O_AH 0
#define O_AL (1*MATB)
#define O_BH (2*MATB)
#define O_BL (3*MATB)
#define DYN_SMEM (NSTG*STGB + 128)
#define NKC (NN/KC)

#define WNSTG 3
#define WMAT (128*128)
#define WSTG (4*WMAT)
#define WDYN (WNSTG*WSTG + 128)

__device__ __nv_bfloat16 g_Whi[NN*NN];
__device__ __nv_bfloat16 g_Wlo[NN*NN];
__device__ __nv_bfloat16 g_Athi[NN*NN];
__device__ __nv_bfloat16 g_Atlo[NN*NN];
__device__ float         g_Vx[NN*BB];
__device__ __nv_bfloat16 g_zbh[2][BB*NN];
__device__ __nv_bfloat16 g_zbl[2][BB*NN];
__device__ double g_nd[3][2];
__device__ unsigned g_arrive, g_release;

__device__ __forceinline__ uint32_t smem_u32(const void* p) {
    uint32_t a;
    asm("{ .reg .u64 t; cvta.to.shared.u64 t, %1; cvt.u32.u64 %0, t; }" : "=r"(a) : "l"(p));
    return a;
}
__device__ __forceinline__ void cp16(uint32_t dst, const void* src) {
    asm volatile("cp.async.cg.shared.global [%0], [%1], 16;" :: "r"(dst), "l"(src) : "memory");
}
#define CP_COMMIT() asm volatile("cp.async.commit_group;" ::: "memory")
#define CP_WAIT(n)  asm volatile("cp.async.wait_group %0;" :: "n"(n) : "memory")
__device__ __forceinline__ void ldsm4(uint32_t* r, uint32_t a) {
    asm volatile("ldmatrix.sync.aligned.m8n8.x4.shared.b16 {%0,%1,%2,%3}, [%4];"
                 : "=r"(r[0]), "=r"(r[1]), "=r"(r[2]), "=r"(r[3]) : "r"(a));
}
__device__ __forceinline__ void mma16816(float* c, const uint32_t* a, uint32_t b0, uint32_t b1) {
    asm volatile("mma.sync.aligned.m16n8k16.row.col.f32.bf16.bf16.f32 "
                 "{%0,%1,%2,%3}, {%4,%5,%6,%7}, {%8,%9}, {%0,%1,%2,%3};"
                 : "+f"(c[0]), "+f"(c[1]), "+f"(c[2]), "+f"(c[3])
                 : "r"(a[0]), "r"(a[1]), "r"(a[2]), "r"(a[3]), "r"(b0), "r"(b1));
}

__global__ void init_kernel() {
    int idx = blockIdx.x * blockDim.x + threadIdx.x;
    if (idx < BB * NN) {
        g_zbh[0][idx] = __float2bfloat16(0.0f);
        g_zbl[0][idx] = __float2bfloat16(0.0f);
    }
    if (idx == 0) {
        for (int i = 0; i < 3; i++) { g_nd[i][0] = 0.0; g_nd[i][1] = 0.0; }
        g_arrive = 0u; g_release = 0u;
    }
}

// At[i][k] = A[k][i], split bf16 hi/lo
__global__ void __launch_bounds__(256) split_at_kernel(const float* __restrict__ A) {
    __shared__ float t[32][33];
    const int i0 = blockIdx.x * 32, k0 = blockIdx.y * 32;
    const int lx = threadIdx.x & 31, ly = threadIdx.x >> 5;
#pragma unroll
    for (int r = 0; r < 32; r += 8)
        t[ly + r][lx] = A[(long)(k0 + ly + r) * NN + i0 + lx];
    __syncthreads();
#pragma unroll
    for (int r = 0; r < 32; r += 8) {
        const float v = t[lx][ly + r];
        const long o = (long)(i0 + ly + r) * NN + k0 + lx;
        __nv_bfloat16 hi = __float2bfloat16_rn(v);
        g_Athi[o] = hi;
        g_Atlo[o] = __float2bfloat16_rn(v - __bfloat162float(hi));
    }
}

// W = (1-m)I - At At^T + S - S^T  (bf16x3 mma), tile 128x128
__global__ void __launch_bounds__(256, 1) build_w_mma_kernel(const float* __restrict__ S,
                                                             const float* __restrict__ m_raw) {
    extern __shared__ __align__(16) char dsm[];
    const uint32_t sbase = (smem_u32(dsm) + 127u) & ~127u;
    const int tid = threadIdx.x, l = tid & 31, warp = tid >> 5;
    const int i0 = blockIdx.x * 128, j0 = blockIdx.y * 128;
    const int wm = (warp >> 2) * 64, wn = (warp & 3) * 32;
    const int r7 = l & 7;
    const int rowA = wm + r7 + ((l >> 3) & 1) * 8;
    const int kgA = (l >> 4) & 1;
    const int rowBb = wn + r7 + ((l >> 4) & 1) * 8;
    const int kgB = (l >> 3) & 1;
    const int ld_r = tid >> 3, ld_c = tid & 7;

    float c[4][4][4];
#pragma unroll
    for (int f = 0; f < 4; f++)
#pragma unroll
        for (int g = 0; g < 4; g++)
#pragma unroll
            for (int q = 0; q < 4; q++) c[f][g][q] = 0.0f;

#define W_LOAD(stg, k0v) do {                                                 \
    const uint32_t sb_ = sbase + (stg) * WSTG;                                \
    _Pragma("unroll")                                                         \
    for (int rep = 0; rep < 4; rep++) {                                       \
        const int r_ = ld_r + rep * 32;                                       \
        const uint32_t d_ = (uint32_t)r_ * 128 + ((uint32_t)(ld_c ^ (r_ & 7)) << 4); \
        const long ga_ = (long)(i0 + r_) * NN + (k0v) + ld_c * 8;             \
        const long gb_ = (long)(j0 + r_) * NN + (k0v) + ld_c * 8;             \
        cp16(sb_ + 0*WMAT + d_, g_Athi + ga_);                                \
        cp16(sb_ + 1*WMAT + d_, g_Atlo + ga_);                                \
        cp16(sb_ + 2*WMAT + d_, g_Athi + gb_);                                \
        cp16(sb_ + 3*WMAT + d_, g_Atlo + gb_);                                \
    } } while (0)

#pragma unroll
    for (int s = 0; s < WNSTG - 1; s++) { W_LOAD(s, s * KC); CP_COMMIT(); }

    for (int kc = 0; kc < NKC; kc++) {
        CP_WAIT(WNSTG - 2);
        __syncthreads();
        if (kc + WNSTG - 1 < NKC) W_LOAD((kc + WNSTG - 1) % WNSTG, (kc + WNSTG - 1) * KC);
        CP_COMMIT();
        const uint32_t sb = sbase + (kc % WNSTG) * WSTG;
#pragma unroll
        for (int s4 = 0; s4 < 4; s4++) {
            const int kg0 = s4 * 2;
            const uint32_t swA = (uint32_t)((kg0 + kgA) ^ r7) << 4;
            const uint32_t swB = (uint32_t)((kg0 + kgB) ^ r7) << 4;
            uint32_t ah[4][4], al[4][4], bh[2][4], bl[2][4];
#pragma unroll
            for (int f = 0; f < 4; f++) {
                ldsm4(ah[f], sb + 0*WMAT + (uint32_t)(rowA + f * 16) * 128 + swA);
                ldsm4(al[f], sb + 1*WMAT + (uint32_t)(rowA + f * 16) * 128 + swA);
            }
#pragma unroll
            for (int g2 = 0; g2 < 2; g2++) {
                ldsm4(bh[g2], sb + 2*WMAT + (uint32_t)(rowBb + g2 * 16) * 128 + swB);
                ldsm4(bl[g2], sb + 3*WMAT + (uint32_t)(rowBb + g2 * 16) * 128 + swB);
            }
#pragma unroll
            for (int f = 0; f < 4; f++)
#pragma unroll
                for (int g2 = 0; g2 < 2; g2++) {
                    mma16816(c[f][g2*2+0], ah[f], bh[g2][0], bh[g2][1]);
                    mma16816(c[f][g2*2+1], ah[f], bh[g2][2], bh[g2][3]);
                    mma16816(c[f][g2*2+0], ah[f], bl[g2][0], bl[g2][1]);
                    mma16816(c[f][g2*2+1], ah[f], bl[g2][2], bl[g2][3]);
                    mma16816(c[f][g2*2+0], al[f], bh[g2][0], bh[g2][1]);
                    mma16816(c[f][g2*2+1], al[f], bh[g2][2], bh[g2][3]);
                }
        }
    }
#undef W_LOAD

    const float m = log1pf(expf(m_raw[0]));
    const float omm = 1.0f - m;
#pragma unroll
    for (int f = 0; f < 4; f++)
#pragma unroll
        for (int g = 0; g < 4; g++)
#pragma unroll
            for (int h = 0; h < 2; h++) {
                const int i = i0 + wm + f * 16 + h * 8 + (l >> 2);
                const int j = j0 + wn + g * 8 + (l & 3) * 2;
                float2 sij = *(const float2*)&S[(long)i * NN + j];
                float w0 = -c[f][g][h*2+0] + sij.x - S[(long)j * NN + i];
                float w1 = -c[f][g][h*2+1] + sij.y - S[(long)(j + 1) * NN + i];
                if (i == j) w0 += omm;
                if (i == j + 1) w1 += omm;
                __nv_bfloat16 h0 = __float2bfloat16_rn(w0);
                __nv_bfloat16 h1 = __float2bfloat16_rn(w1);
                *(__nv_bfloat162*)&g_Whi[(long)i * NN + j] = __halves2bfloat162(h0, h1);
                *(__nv_bfloat162*)&g_Wlo[(long)i * NN + j] = __halves2bfloat162(
                    __float2bfloat16_rn(w0 - __bfloat162float(h0)),
                    __float2bfloat16_rn(w1 - __bfloat162float(h1)));
            }
}

#define TMW 64
#define KTW 16
#define PADW 68
__global__ void __launch_bounds__(256) build_vx_kernel(const float* __restrict__ U,
                                                       const float* __restrict__ b,
                                                       const float* __restrict__ x) {
    __shared__ __align__(16) float Us[KTW][PADW];
    __shared__ __align__(16) float Xs[KTW][PADW];
    const int i0 = blockIdx.x * TMW, j0 = blockIdx.y * TMW;
    const int tx = threadIdx.x & 15, ty = threadIdx.x >> 4;
    float acc[4][4];
#pragma unroll
    for (int a = 0; a < 4; a++)
#pragma unroll
        for (int cc = 0; cc < 4; cc++) acc[a][cc] = 0.0f;
    for (int k0 = 0; k0 < DD; k0 += KTW) {
#pragma unroll
        for (int t = threadIdx.x; t < KTW * TMW; t += 256) {
            int rr = t >> 4, cc = t & 15;
            Us[cc][rr] = U[(i0 + rr) * DD + k0 + cc];
            Xs[cc][rr] = x[(j0 + rr) * DD + k0 + cc];
        }
        __syncthreads();
#pragma unroll
        for (int k = 0; k < KTW; k++) {
            float4 av = *(const float4*)&Us[k][ty * 4];
            float4 bv = *(const float4*)&Xs[k][tx * 4];
            float am[4] = {av.x, av.y, av.z, av.w};
            float bn[4] = {bv.x, bv.y, bv.z, bv.w};
#pragma unroll
            for (int mi = 0; mi < 4; mi++)
#pragma unroll
                for (int ni = 0; ni < 4; ni++) acc[mi][ni] += am[mi] * bn[ni];
        }
        __syncthreads();
    }
#pragma unroll
    for (int mi = 0; mi < 4; mi++) {
        const int i = i0 + ty * 4 + mi;
        const float bi = b[i];
#pragma unroll
        for (int ni = 0; ni < 4; ni++)
            g_Vx[i * BB + j0 + tx * 4 + ni] = acc[mi][ni] + bi;
    }
}

__device__ __forceinline__ void grid_barrier(unsigned& gen) {
    __syncthreads();
    if (threadIdx.x == 0) {
        gen++;
        __threadfence();
        unsigned prev = atomicAdd(&g_arrive, 1u);
        if (prev == SB - 1) {
            atomicExch(&g_arrive, 0u);
            __threadfence();
            atomicExch(&g_release, gen);
        } else {
            while (*(volatile unsigned*)&g_release < gen) { }
            __threadfence();
        }
    }
    __syncthreads();
}

__global__ void __launch_bounds__(256, 1) solve_kernel(float* __restrict__ out) {
    extern __shared__ __align__(16) char dsm[];
    const uint32_t sbase = (smem_u32(dsm) + 127u) & ~127u;
    __shared__ float sredD[8], sredN[8];

    const int tid = threadIdx.x, l = tid & 31, warp = tid >> 5;
    const int i0 = (blockIdx.x >> 2) * 64, j0 = (blockIdx.x & 3) * 64;
    const int wm = (warp >> 2) * 32, wn = (warp & 3) * 16;
    const int r7 = l & 7;
    const int rowA0 = wm + r7 + ((l >> 3) & 1) * 8;
    const int kgA = (l >> 4) & 1;
    const int rowB = wn + r7 + ((l >> 4) & 1) * 8;
    const int kgB = (l >> 3) & 1;
    const int ld_r0 = tid >> 3, ld_c = tid & 7;
    const uint32_t ld_s0 = ((uint32_t)(ld_c ^ (ld_r0 & 7))) << 4;
    const int ld_r1 = ld_r0 + 32;
    const uint32_t ld_s1 = ((uint32_t)(ld_c ^ (ld_r1 & 7))) << 4;

    float zr[2][2][2][2], vx[2][2][2][2];
#pragma unroll
    for (int f = 0; f < 2; f++)
#pragma unroll
        for (int g = 0; g < 2; g++)
#pragma unroll
            for (int h = 0; h < 2; h++) {
                const int i = i0 + wm + f * 16 + h * 8 + (l >> 2);
                const int j = j0 + wn + g * 8 + (l & 3) * 2;
                float2 v = *(const float2*)&g_Vx[i * BB + j];
                vx[f][g][h][0] = v.x; vx[f][g][h][1] = v.y;
                zr[f][g][h][0] = 0.0f; zr[f][g][h][1] = 0.0f;
            }

#define S_LOAD(stg, k0v, zhp, zlp) do {                                       \
    const uint32_t sb_ = sbase + (stg) * STGB;                                \
    const long gW0_ = (long)(i0 + ld_r0) * NN + (k0v) + ld_c * 8;             \
    const long gW1_ = (long)(i0 + ld_r1) * NN + (k0v) + ld_c * 8;             \
    const long gZ0_ = (long)(j0 + ld_r0) * NN + (k0v) + ld_c * 8;             \
    const long gZ1_ = (long)(j0 + ld_r1) * NN + (k0v) + ld_c * 8;             \
    const uint32_t d0_ = (uint32_t)ld_r0 * 128 + ld_s0;                       \
    const uint32_t d1_ = (uint32_t)ld_r1 * 128 + ld_s1;                       \
    cp16(sb_ + O_AH + d0_, g_Whi + gW0_);                                     \
    cp16(sb_ + O_AH + d1_, g_Whi + gW1_);                                     \
    cp16(sb_ + O_AL + d0_, g_Wlo + gW0_);                                     \
    cp16(sb_ + O_AL + d1_, g_Wlo + gW1_);                                     \
    cp16(sb_ + O_BH + d0_, (zhp) + gZ0_);                                     \
    cp16(sb_ + O_BH + d1_, (zhp) + gZ1_);                                     \
    cp16(sb_ + O_BL + d0_, (zlp) + gZ0_);                                     \
    cp16(sb_ + O_BL + d1_, (zlp) + gZ1_);                                     \
    } while (0)

    unsigned gen = 0;
    int cur = 0, it = 0;

    while (1) {
        it++;
        const __nv_bfloat16* __restrict__ zh = g_zbh[cur];
        const __nv_bfloat16* __restrict__ zl = g_zbl[cur];
        float c[2][2][4];
#pragma unroll
        for (int f = 0; f < 2; f++)
#pragma unroll
            for (int g = 0; g < 2; g++)
#pragma unroll
                for (int q = 0; q < 4; q++) c[f][g][q] = 0.0f;

#pragma unroll
        for (int s = 0; s < NSTG - 1; s++) { S_LOAD(s, s * KC, zh, zl); CP_COMMIT(); }

        for (int kc = 0; kc < NKC; kc++) {
            CP_WAIT(NSTG - 2);
            __syncthreads();
            if (kc + NSTG - 1 < NKC)
                S_LOAD((kc + NSTG - 1) % NSTG, (kc + NSTG - 1) * KC, zh, zl);
            CP_COMMIT();
            const uint32_t sb = sbase + (kc % NSTG) * STGB;
#pragma unroll
            for (int s4 = 0; s4 < 4; s4++) {
                const int kg0 = s4 * 2;
                const uint32_t swA = (uint32_t)((kg0 + kgA) ^ r7) << 4;
                const uint32_t swB = (uint32_t)((kg0 + kgB) ^ r7) << 4;
                uint32_t ah0[4], ah1[4], al0[4], al1[4], bh[4], bl[4];
                ldsm4(ah0, sb + O_AH + (uint32_t)rowA0 * 128 + swA);
                ldsm4(ah1, sb + O_AH + (uint32_t)(rowA0 + 16) * 128 + swA);
                ldsm4(al0, sb + O_AL + (uint32_t)rowA0 * 128 + swA);
                ldsm4(al1, sb + O_AL + (uint32_t)(rowA0 + 16) * 128 + swA);
                ldsm4(bh, sb + O_BH + (uint32_t)rowB * 128 + swB);
                ldsm4(bl, sb + O_BL + (uint32_t)rowB * 128 + swB);
                mma16816(c[0][0], ah0, bh[0], bh[1]);
                mma16816(c[0][1], ah0, bh[2], bh[3]);
                mma16816(c[1][0], ah1, bh[0], bh[1]);
                mma16816(c[1][1], ah1, bh[2], bh[3]);
                mma16816(c[0][0], ah0, bl[0], bl[1]);
                mma16816(c[0][1], ah0, bl[2], bl[3]);
                mma16816(c[1][0], ah1, bl[0], bl[1]);
                mma16816(c[1][1], ah1, bl[2], bl[3]);
                mma16816(c[0][0], al0, bh[0], bh[1]);
                mma16816(c[0][1], al0, bh[2], bh[3]);
                mma16816(c[1][0], al1, bh[0], bh[1]);
                mma16816(c[1][1], al1, bh[2], bh[3]);
            }
        }

        __nv_bfloat16* __restrict__ zhn = g_zbh[cur ^ 1];
        __nv_bfloat16* __restrict__ zln = g_zbl[cur ^ 1];
        float d2 = 0.0f, n2 = 0.0f;
#pragma unroll
        for (int f = 0; f < 2; f++)
#pragma unroll
            for (int g = 0; g < 2; g++)
#pragma unroll
                for (int h = 0; h < 2; h++) {
                    const int i = i0 + wm + f * 16 + h * 8 + (l >> 2);
                    const int j = j0 + wn + g * 8 + (l & 3) * 2;
#pragma unroll
                    for (int p = 0; p < 2; p++) {
                        const float zv = zr[f][g][h][p];
                        float v = 0.9f * zv + 0.1f * (c[f][g][h*2+p] + vx[f][g][h][p]);
                        float r = v > 0.0f ? v : 0.0f;
                        zr[f][g][h][p] = r;
                        __nv_bfloat16 hi = __float2bfloat16_rn(r);
                        zhn[(j + p) * NN + i] = hi;
                        zln[(j + p) * NN + i] = __float2bfloat16_rn(r - __bfloat162float(hi));
                        const float dd = r - zv;
                        d2 += dd * dd;
                        n2 += zv * zv;
                    }
                }
#pragma unroll
        for (int off = 16; off; off >>= 1) {
            d2 += __shfl_xor_sync(0xffffffffu, d2, off);
            n2 += __shfl_xor_sync(0xffffffffu, n2, off);
        }
        if (l == 0) { sredD[warp] = d2; sredN[warp] = n2; }
        __syncthreads();
        const int nb = it % 3;
        if (tid == 0) {
            double Dd = 0.0, Nd = 0.0;
#pragma unroll
            for (int w = 0; w < 8; w++) { Dd += (double)sredD[w]; Nd += (double)sredN[w]; }
            atomicAdd(&g_nd[nb][0], Dd);
            atomicAdd(&g_nd[nb][1], Nd);
        }

        grid_barrier(gen);

        const double Dt = *(volatile double*)&g_nd[nb][0];
        const double Nt = *(volatile double*)&g_nd[nb][1];
        const double err = sqrt(Dt) / (sqrt(Nt) + 1e-12);
        if (blockIdx.x == 0 && tid == 0) {
            const int rb = (it + 2) % 3;
            *(volatile double*)&g_nd[rb][0] = 0.0;
            *(volatile double*)&g_nd[rb][1] = 0.0;
            __threadfence();
        }
        cur ^= 1;
        if (it >= MAXIT || err < 1e-4) break;
    }
#undef S_LOAD

#pragma unroll
    for (int f = 0; f < 2; f++)
#pragma unroll
        for (int g = 0; g < 2; g++)
#pragma unroll
            for (int h = 0; h < 2; h++) {
                const int i = i0 + wm + f * 16 + h * 8 + (l >> 2);
                const int j = j0 + wn + g * 8 + (l & 3) * 2;
                float2 v;
                v.x = zr[f][g][h][0];
                v.y = zr[f][g][h][1];
                *(float2*)&out[i * BB + j] = v;
            }
}

extern "C" void kernel_launch(void* const* d_in, const int* in_sizes, int n_in,
                              void* d_out, int out_size) {
    const float* A     = (const float*)d_in[0];
    const float* S     = (const float*)d_in[1];
    const float* m_raw = (const float*)d_in[2];
    const float* U     = (const float*)d_in[3];
    const float* b     = (const float*)d_in[4];
    const float* x     = (const float*)d_in[5];
    float* out = (float*)d_out;

    cudaFuncSetAttribute(solve_kernel, cudaFuncAttributeMaxDynamicSharedMemorySize, DYN_SMEM);
    cudaFuncSetAttribute(build_w_mma_kernel, cudaFuncAttributeMaxDynamicSharedMemorySize, WDYN);

    init_kernel<<<(BB * NN + 255) / 256, 256>>>();
    dim3 gt(NN / 32, NN / 32);
    split_at_kernel<<<gt, 256>>>(A);
    dim3 gw(NN / 128, NN / 128);
    build_w_mma_kernel<<<gw, 256, WDYN>>>(S, m_raw);
    dim3 gv(NN / TMW, BB / TMW);
    build_vx_kernel<<<gv, 256>>>(U, b, x);
    solve_kernel<<<SB, 256, DYN_SMEM>>>(out);
}